// round 2
// baseline (speedup 1.0000x reference)
#include <cuda_runtime.h>
#include <cuda_bf16.h>
#include <cstdint>
#include <cstddef>

// ---------------- problem constants ----------------
#define T_LEN 128
#define BATCH 32
#define HID   1024
#define VOCAB 32000
#define MROWS (T_LEN * BATCH)        // 4096
#define LOGITS_ELEMS ((size_t)MROWS * VOCAB)   // 131072000
#define HIDDEN_ELEMS (2 * BATCH * HID)         // 65536

// ---------------- device scratch (no runtime alloc allowed) ----------------
__device__ float g_x [MROWS * HID];   // current layer input / output sequence (16 MB)
__device__ float g_xw[MROWS * HID];   // precomputed input projection         (16 MB)
__device__ float g_h [2 * BATCH * HID]; // ping-pong hidden state

// =====================================================================
// Embedding gather: one block per (t,b) row, 256 threads x float4 = 1024 f
// =====================================================================
__global__ __launch_bounds__(256)
void embed_k(const int* __restrict__ idx, const float* __restrict__ emb,
             float* __restrict__ xout)
{
    int row = blockIdx.x;
    int tok = idx[row];
    const float4* s = (const float4*)(emb + (size_t)tok * HID);
    float4* d = (float4*)(xout + (size_t)row * HID);
    d[threadIdx.x] = s[threadIdx.x];
}

// =====================================================================
// tf32 tensor-core GEMM:  C[M,N] = A[M,K] * B[N,K]^T (+bias) (+=C)
// BM=128 BN=128 BK=32, 256 threads, 8 warps (2x4), warp tile 64x32,
// mma.sync.aligned.m16n8k8.row.col.f32.tf32.tf32.f32
// akind/bkind: 0 = round-to-tf32(v), 1 = round-to-tf32(v - tf32(v)) (residual)
// =====================================================================
#define BM 128
#define BN 128
#define BK 32
#define SAPAD 132

__device__ __forceinline__ float stage_cvt(float v, int kind)
{
    uint32_t t;
    asm("cvt.rna.tf32.f32 %0, %1;" : "=r"(t) : "f"(v));
    float hi = __uint_as_float(t);
    if (kind == 0) return hi;
    float r = v - hi;
    uint32_t t2;
    asm("cvt.rna.tf32.f32 %0, %1;" : "=r"(t2) : "f"(r));
    return __uint_as_float(t2);
}

__device__ __forceinline__ void mma_tf32(float c[4], uint32_t a0, uint32_t a1,
                                         uint32_t a2, uint32_t a3,
                                         uint32_t b0, uint32_t b1)
{
    asm volatile(
        "mma.sync.aligned.m16n8k8.row.col.f32.tf32.tf32.f32 "
        "{%0,%1,%2,%3}, {%4,%5,%6,%7}, {%8,%9}, {%0,%1,%2,%3};"
        : "+f"(c[0]), "+f"(c[1]), "+f"(c[2]), "+f"(c[3])
        : "r"(a0), "r"(a1), "r"(a2), "r"(a3), "r"(b0), "r"(b1));
}

__global__ __launch_bounds__(256)
void gemm_tf32(const float* __restrict__ A, const float* __restrict__ B,
               float* __restrict__ C, const float* __restrict__ bias,
               int M, int N, int K, int akind, int bkind, int accumulate)
{
    __shared__ float As[BK][SAPAD];
    __shared__ float Bs[BK][SAPAD];

    int tid  = threadIdx.x;
    int warp = tid >> 5, lane = tid & 31;
    int wm   = warp >> 2;          // 0..1  (64-row slab)
    int wn   = warp & 3;           // 0..3  (32-col slab)
    int gID  = lane >> 2;          // 0..7
    int tig  = lane & 3;           // 0..3

    int rowBase = blockIdx.x * BM;
    int colBase = blockIdx.y * BN;

    // loader mapping: tid -> (k-quad, row)
    int lc4 = tid & 7;             // 0..7  : k = lc4*4 .. +3
    int lr  = tid >> 3;            // 0..31 : rows lr + i*32
    const float* Aload = A + (size_t)(rowBase + lr) * K + lc4 * 4;
    const float* Bload = B + (size_t)(colBase + lr) * K + lc4 * 4;

    float4 aReg[4], bReg[4];

    float acc[4][4][4];
#pragma unroll
    for (int mt = 0; mt < 4; mt++)
#pragma unroll
        for (int nt = 0; nt < 4; nt++)
#pragma unroll
            for (int q = 0; q < 4; q++) acc[mt][nt][q] = 0.f;

    const int NT = K / BK;

    // initial tile load + stage
#pragma unroll
    for (int i = 0; i < 4; i++) {
        aReg[i] = *(const float4*)(Aload + (size_t)i * 32 * K);
        bReg[i] = *(const float4*)(Bload + (size_t)i * 32 * K);
    }
#pragma unroll
    for (int i = 0; i < 4; i++) {
        int m = lr + i * 32;
        float va[4] = {aReg[i].x, aReg[i].y, aReg[i].z, aReg[i].w};
        float vb[4] = {bReg[i].x, bReg[i].y, bReg[i].z, bReg[i].w};
#pragma unroll
        for (int q = 0; q < 4; q++) {
            As[lc4 * 4 + q][m] = stage_cvt(va[q], akind);
            Bs[lc4 * 4 + q][m] = stage_cvt(vb[q], bkind);
        }
    }
    __syncthreads();

    for (int kt = 0; kt < NT; kt++) {
        if (kt + 1 < NT) {
            const float* ap = Aload + (size_t)(kt + 1) * BK;
            const float* bp = Bload + (size_t)(kt + 1) * BK;
#pragma unroll
            for (int i = 0; i < 4; i++) {
                aReg[i] = *(const float4*)(ap + (size_t)i * 32 * K);
                bReg[i] = *(const float4*)(bp + (size_t)i * 32 * K);
            }
        }
#pragma unroll
        for (int ks = 0; ks < 4; ks++) {
            int kb = ks * 8;
            uint32_t af[4][4];
#pragma unroll
            for (int mt = 0; mt < 4; mt++) {
                int m0 = wm * 64 + mt * 16 + gID;
                af[mt][0] = __float_as_uint(As[kb + tig    ][m0    ]);
                af[mt][1] = __float_as_uint(As[kb + tig    ][m0 + 8]);
                af[mt][2] = __float_as_uint(As[kb + tig + 4][m0    ]);
                af[mt][3] = __float_as_uint(As[kb + tig + 4][m0 + 8]);
            }
#pragma unroll
            for (int nt = 0; nt < 4; nt++) {
                int n0 = wn * 32 + nt * 8 + gID;
                uint32_t b0 = __float_as_uint(Bs[kb + tig    ][n0]);
                uint32_t b1 = __float_as_uint(Bs[kb + tig + 4][n0]);
#pragma unroll
                for (int mt = 0; mt < 4; mt++)
                    mma_tf32(acc[mt][nt], af[mt][0], af[mt][1], af[mt][2],
                             af[mt][3], b0, b1);
            }
        }
        __syncthreads();
        if (kt + 1 < NT) {
#pragma unroll
            for (int i = 0; i < 4; i++) {
                int m = lr + i * 32;
                float va[4] = {aReg[i].x, aReg[i].y, aReg[i].z, aReg[i].w};
                float vb[4] = {bReg[i].x, bReg[i].y, bReg[i].z, bReg[i].w};
#pragma unroll
                for (int q = 0; q < 4; q++) {
                    As[lc4 * 4 + q][m] = stage_cvt(va[q], akind);
                    Bs[lc4 * 4 + q][m] = stage_cvt(vb[q], bkind);
                }
            }
            __syncthreads();
        }
    }

    // epilogue
#pragma unroll
    for (int mt = 0; mt < 4; mt++) {
#pragma unroll
        for (int nt = 0; nt < 4; nt++) {
            int r0 = rowBase + wm * 64 + mt * 16 + gID;
            int c0 = colBase + wn * 32 + nt * 8 + tig * 2;
            float bi0 = 0.f, bi1 = 0.f;
            if (bias) { bi0 = bias[c0]; bi1 = bias[c0 + 1]; }
            float* p0 = C + (size_t)r0 * N + c0;
            float* p1 = C + (size_t)(r0 + 8) * N + c0;
            float2 o0 = make_float2(acc[mt][nt][0] + bi0, acc[mt][nt][1] + bi1);
            float2 o1 = make_float2(acc[mt][nt][2] + bi0, acc[mt][nt][3] + bi1);
            if (accumulate) {
                float2 e0 = *(const float2*)p0;
                float2 e1 = *(const float2*)p1;
                o0.x += e0.x; o0.y += e0.y;
                o1.x += e1.x; o1.y += e1.y;
            }
            *(float2*)p0 = o0;
            *(float2*)p1 = o1;
        }
    }
}

// =====================================================================
// RNN recurrence step:  h_new = tanh(xw[t] + h_in @ Whh^T + bhh)
// grid (4, 32): b-tile of 8, j-tile of 32. 256 threads: thread = (b, j).
// h tile staged in padded smem (bank-broadcast, conflict free).
// =====================================================================
__global__ __launch_bounds__(256)
void rnn_step(const float* __restrict__ xw,    // [32][1024] (this t)
              const float* __restrict__ h_in,  // [32][1024]
              const float* __restrict__ Whh,   // [1024][1024]
              const float* __restrict__ bhh,   // [1024]
              float* __restrict__ h_out,       // [32][1024]
              float* __restrict__ y_out)       // [32][1024] (sequence slot)
{
    __shared__ float sh[8][1028];
    int tid = threadIdx.x;
    int b0 = blockIdx.x * 8;

    for (int i = tid; i < 2048; i += 256) {       // 8 rows x 256 float4
        int r = i >> 8;
        int c = i & 255;
        float4 v = *(const float4*)(h_in + (size_t)(b0 + r) * HID + c * 4);
        *(float4*)&sh[r][c * 4] = v;
    }
    __syncthreads();

    int lb = tid & 7;
    int jj = tid >> 3;
    int j = blockIdx.y * 32 + jj;
    int b = b0 + lb;

    const float4* wr = (const float4*)(Whh + (size_t)j * HID);
    const float4* hr = (const float4*)&sh[lb][0];

    float acc = 0.f;
#pragma unroll 8
    for (int k = 0; k < HID / 4; k++) {
        float4 w = wr[k];
        float4 h = hr[k];
        acc += w.x * h.x + w.y * h.y + w.z * h.z + w.w * h.w;
    }
    float pre = xw[(size_t)b * HID + j] + bhh[j] + acc;
    float v = tanhf(pre);
    h_out[(size_t)b * HID + j] = v;
    y_out[(size_t)b * HID + j] = v;
}

// =====================================================================
// In-place log_softmax over rows of 32000. Row cached in 128 KB smem.
// =====================================================================
__global__ __launch_bounds__(256)
void logsoftmax_k(float* __restrict__ out)
{
    extern __shared__ float srow[];
    __shared__ float red[256];
    int tid = threadIdx.x;
    float4* p4 = (float4*)(out + (size_t)blockIdx.x * VOCAB);

    float m = -3.4e38f;
    for (int i = tid; i < VOCAB / 4; i += 256) {
        float4 v = p4[i];
        *(float4*)&srow[i * 4] = v;
        m = fmaxf(m, fmaxf(fmaxf(v.x, v.y), fmaxf(v.z, v.w)));
    }
    red[tid] = m; __syncthreads();
    for (int s = 128; s > 0; s >>= 1) {
        if (tid < s) red[tid] = fmaxf(red[tid], red[tid + s]);
        __syncthreads();
    }
    float rm = red[0]; __syncthreads();

    float sum = 0.f;
    for (int i = tid; i < VOCAB; i += 256) sum += expf(srow[i] - rm);
    red[tid] = sum; __syncthreads();
    for (int s = 128; s > 0; s >>= 1) {
        if (tid < s) red[tid] += red[tid + s];
        __syncthreads();
    }
    float lz = rm + logf(red[0]);

    for (int i = tid; i < VOCAB / 4; i += 256) {
        float4 v = *(float4*)&srow[i * 4];
        v.x -= lz; v.y -= lz; v.z -= lz; v.w -= lz;
        p4[i] = v;
    }
}

// =====================================================================
// host orchestration (graph-capturable: kernels + async D2D copies only)
// =====================================================================
extern "C" void kernel_launch(void* const* d_in, const int* in_sizes, int n_in,
                              void* d_out, int out_size)
{
    const int*   input_x = (const int*)  d_in[0];
    const float* hidden  = (const float*)d_in[1];
    const float* emb     = (const float*)d_in[2];
    const float* W_ih    = (const float*)d_in[3];
    const float* W_hh    = (const float*)d_in[4];
    const float* b_ih    = (const float*)d_in[5];
    const float* b_hh    = (const float*)d_in[6];
    const float* W_out   = (const float*)d_in[7];
    const float* b_out   = (const float*)d_in[8];
    float* out = (float*)d_out;

    float *gx, *gxw, *gh;
    cudaGetSymbolAddress((void**)&gx,  g_x);
    cudaGetSymbolAddress((void**)&gxw, g_xw);
    cudaGetSymbolAddress((void**)&gh,  g_h);
    float* ph0 = gh;
    float* ph1 = gh + BATCH * HID;

    cudaFuncSetAttribute(logsoftmax_k,
                         cudaFuncAttributeMaxDynamicSharedMemorySize,
                         VOCAB * (int)sizeof(float));

    const int writeHidden =
        (size_t)out_size >= LOGITS_ELEMS + HIDDEN_ELEMS;

    // 1) embedding gather
    embed_k<<<MROWS, 256>>>(input_x, emb, gx);

    for (int l = 0; l < 2; l++) {
        const float* Wi = W_ih + (size_t)l * HID * HID;
        const float* Wh = W_hh + (size_t)l * HID * HID;
        const float* bi = b_ih + (size_t)l * HID;
        const float* bh = b_hh + (size_t)l * HID;

        // init hidden
        cudaMemcpyAsync(ph0, hidden + (size_t)l * BATCH * HID,
                        (size_t)BATCH * HID * sizeof(float),
                        cudaMemcpyDeviceToDevice, 0);

        // input projection, 3-pass tf32 split (near-fp32 accuracy)
        dim3 gp(MROWS / BM, HID / BN);
        gemm_tf32<<<gp, 256>>>(gx, Wi, gxw, bi, MROWS, HID, HID, 0, 0, 0);
        gemm_tf32<<<gp, 256>>>(gx, Wi, gxw, nullptr, MROWS, HID, HID, 1, 0, 1);
        gemm_tf32<<<gp, 256>>>(gx, Wi, gxw, nullptr, MROWS, HID, HID, 0, 1, 1);

        // sequential recurrence (fp32 exact)
        for (int t = 0; t < T_LEN; t++) {
            float* hin  = (t & 1) ? ph1 : ph0;
            float* hout = (t & 1) ? ph0 : ph1;
            rnn_step<<<dim3(4, 32), 256>>>(gxw + (size_t)t * BATCH * HID,
                                           hin, Wh, bh, hout,
                                           gx + (size_t)t * BATCH * HID);
        }

        // new_hidden[l] = y[T-1]
        if (writeHidden)
            cudaMemcpyAsync(out + LOGITS_ELEMS + (size_t)l * BATCH * HID,
                            gx + (size_t)(T_LEN - 1) * BATCH * HID,
                            (size_t)BATCH * HID * sizeof(float),
                            cudaMemcpyDeviceToDevice, 0);
    }

    // output projection (single-pass tf32, no error accumulation downstream)
    dim3 go(MROWS / BM, VOCAB / BN);
    gemm_tf32<<<go, 256>>>(gx, W_out, out, b_out, MROWS, VOCAB, HID, 0, 0, 0);

    // in-place log_softmax
    logsoftmax_k<<<MROWS, 256, VOCAB * (int)sizeof(float)>>>(out);
}

// round 3
// speedup vs baseline: 1.0705x; 1.0705x over previous
#include <cuda_runtime.h>
#include <cuda_bf16.h>
#include <cstdint>
#include <cstddef>

// ---------------- problem constants ----------------
#define T_LEN 128
#define BATCH 32
#define HID   1024
#define VOCAB 32000
#define MROWS (T_LEN * BATCH)        // 4096
#define LOGITS_ELEMS ((size_t)MROWS * VOCAB)   // 131072000
#define HIDDEN_ELEMS (2 * BATCH * HID)         // 65536

// ---------------- device scratch (no runtime alloc allowed) ----------------
__device__ float g_x [MROWS * HID];     // layer input / output sequence (16 MB)
__device__ float g_xw[MROWS * HID];     // precomputed input projection  (16 MB)
__device__ float g_h [2 * BATCH * HID]; // ping-pong hidden state
__device__ int   g_flags[128];          // persistent-kernel grid barrier flags

// =====================================================================
// Embedding gather
// =====================================================================
__global__ __launch_bounds__(256)
void embed_k(const int* __restrict__ idx, const float* __restrict__ emb,
             float* __restrict__ xout)
{
    int row = blockIdx.x;
    int tok = idx[row];
    const float4* s = (const float4*)(emb + (size_t)tok * HID);
    float4* d = (float4*)(xout + (size_t)row * HID);
    d[threadIdx.x] = s[threadIdx.x];
}

// =====================================================================
// tf32 helpers
// =====================================================================
__device__ __forceinline__ float tf32_hi(float v)
{
    uint32_t t;
    asm("cvt.rna.tf32.f32 %0, %1;" : "=r"(t) : "f"(v));
    return __uint_as_float(t);
}
__device__ __forceinline__ void split_cvt(float v, float& hi, float& lo)
{
    hi = tf32_hi(v);
    lo = tf32_hi(v - hi);
}

__device__ __forceinline__ void mma_tf32(float c[4], uint32_t a0, uint32_t a1,
                                         uint32_t a2, uint32_t a3,
                                         uint32_t b0, uint32_t b1)
{
    asm volatile(
        "mma.sync.aligned.m16n8k8.row.col.f32.tf32.tf32.f32 "
        "{%0,%1,%2,%3}, {%4,%5,%6,%7}, {%8,%9}, {%0,%1,%2,%3};"
        : "+f"(c[0]), "+f"(c[1]), "+f"(c[2]), "+f"(c[3])
        : "r"(a0), "r"(a1), "r"(a2), "r"(a3), "r"(b0), "r"(b1));
}

#define BM 128
#define BN 128
#define BK 32
#define SAPAD 132

// =====================================================================
// Single-pass tf32 GEMM (output projection): C = A[M,K] * B[N,K]^T + bias
// =====================================================================
__global__ __launch_bounds__(256)
void gemm_tf32(const float* __restrict__ A, const float* __restrict__ B,
               float* __restrict__ C, const float* __restrict__ bias,
               int M, int N, int K)
{
    __shared__ float As[BK][SAPAD];
    __shared__ float Bs[BK][SAPAD];

    int tid  = threadIdx.x;
    int warp = tid >> 5, lane = tid & 31;
    int wm   = warp >> 2;
    int wn   = warp & 3;
    int gID  = lane >> 2;
    int tig  = lane & 3;

    int rowBase = blockIdx.x * BM;
    int colBase = blockIdx.y * BN;

    int lc4 = tid & 7;
    int lr  = tid >> 3;
    const float* Aload = A + (size_t)(rowBase + lr) * K + lc4 * 4;
    const float* Bload = B + (size_t)(colBase + lr) * K + lc4 * 4;

    float4 aReg[4], bReg[4];

    float acc[4][4][4];
#pragma unroll
    for (int mt = 0; mt < 4; mt++)
#pragma unroll
        for (int nt = 0; nt < 4; nt++)
#pragma unroll
            for (int q = 0; q < 4; q++) acc[mt][nt][q] = 0.f;

    const int NT = K / BK;

#pragma unroll
    for (int i = 0; i < 4; i++) {
        aReg[i] = *(const float4*)(Aload + (size_t)i * 32 * K);
        bReg[i] = *(const float4*)(Bload + (size_t)i * 32 * K);
    }
#pragma unroll
    for (int i = 0; i < 4; i++) {
        int m = lr + i * 32;
        float va[4] = {aReg[i].x, aReg[i].y, aReg[i].z, aReg[i].w};
        float vb[4] = {bReg[i].x, bReg[i].y, bReg[i].z, bReg[i].w};
#pragma unroll
        for (int q = 0; q < 4; q++) {
            As[lc4 * 4 + q][m] = tf32_hi(va[q]);
            Bs[lc4 * 4 + q][m] = tf32_hi(vb[q]);
        }
    }
    __syncthreads();

    for (int kt = 0; kt < NT; kt++) {
        if (kt + 1 < NT) {
            const float* ap = Aload + (size_t)(kt + 1) * BK;
            const float* bp = Bload + (size_t)(kt + 1) * BK;
#pragma unroll
            for (int i = 0; i < 4; i++) {
                aReg[i] = *(const float4*)(ap + (size_t)i * 32 * K);
                bReg[i] = *(const float4*)(bp + (size_t)i * 32 * K);
            }
        }
#pragma unroll
        for (int ks = 0; ks < 4; ks++) {
            int kb = ks * 8;
            uint32_t af[4][4];
#pragma unroll
            for (int mt = 0; mt < 4; mt++) {
                int m0 = wm * 64 + mt * 16 + gID;
                af[mt][0] = __float_as_uint(As[kb + tig    ][m0    ]);
                af[mt][1] = __float_as_uint(As[kb + tig    ][m0 + 8]);
                af[mt][2] = __float_as_uint(As[kb + tig + 4][m0    ]);
                af[mt][3] = __float_as_uint(As[kb + tig + 4][m0 + 8]);
            }
#pragma unroll
            for (int nt = 0; nt < 4; nt++) {
                int n0 = wn * 32 + nt * 8 + gID;
                uint32_t b0 = __float_as_uint(Bs[kb + tig    ][n0]);
                uint32_t b1 = __float_as_uint(Bs[kb + tig + 4][n0]);
#pragma unroll
                for (int mt = 0; mt < 4; mt++)
                    mma_tf32(acc[mt][nt], af[mt][0], af[mt][1], af[mt][2],
                             af[mt][3], b0, b1);
            }
        }
        __syncthreads();
        if (kt + 1 < NT) {
#pragma unroll
            for (int i = 0; i < 4; i++) {
                int m = lr + i * 32;
                float va[4] = {aReg[i].x, aReg[i].y, aReg[i].z, aReg[i].w};
                float vb[4] = {bReg[i].x, bReg[i].y, bReg[i].z, bReg[i].w};
#pragma unroll
                for (int q = 0; q < 4; q++) {
                    As[lc4 * 4 + q][m] = tf32_hi(va[q]);
                    Bs[lc4 * 4 + q][m] = tf32_hi(vb[q]);
                }
            }
            __syncthreads();
        }
    }

#pragma unroll
    for (int mt = 0; mt < 4; mt++) {
#pragma unroll
        for (int nt = 0; nt < 4; nt++) {
            int r0 = rowBase + wm * 64 + mt * 16 + gID;
            int c0 = colBase + wn * 32 + nt * 8 + tig * 2;
            float bi0 = bias ? bias[c0] : 0.f;
            float bi1 = bias ? bias[c0 + 1] : 0.f;
            float* p0 = C + (size_t)r0 * N + c0;
            float* p1 = C + (size_t)(r0 + 8) * N + c0;
            *(float2*)p0 = make_float2(acc[mt][nt][0] + bi0, acc[mt][nt][1] + bi1);
            *(float2*)p1 = make_float2(acc[mt][nt][2] + bi0, acc[mt][nt][3] + bi1);
        }
    }
}

// =====================================================================
// Fused 3-term tf32 split GEMM (near-fp32): C = A*B^T + bias in ONE pass.
// Stages hi/lo decompositions of both operands; acc += Ah*Bh + Al*Bh + Ah*Bl.
// Dynamic smem: 4 tiles of [BK][SAPAD] = 67.6 KB.
// =====================================================================
__global__ __launch_bounds__(256)
void gemm_split3(const float* __restrict__ A, const float* __restrict__ B,
                 float* __restrict__ C, const float* __restrict__ bias,
                 int M, int N, int K)
{
    extern __shared__ float smem[];
    float* Ah = smem;
    float* Al = smem + BK * SAPAD;
    float* Bh = smem + 2 * BK * SAPAD;
    float* Bl = smem + 3 * BK * SAPAD;

    int tid  = threadIdx.x;
    int warp = tid >> 5, lane = tid & 31;
    int wm   = warp >> 2;
    int wn   = warp & 3;
    int gID  = lane >> 2;
    int tig  = lane & 3;

    int rowBase = blockIdx.x * BM;
    int colBase = blockIdx.y * BN;

    int lc4 = tid & 7;
    int lr  = tid >> 3;
    const float* Aload = A + (size_t)(rowBase + lr) * K + lc4 * 4;
    const float* Bload = B + (size_t)(colBase + lr) * K + lc4 * 4;

    float acc[4][4][4];
#pragma unroll
    for (int mt = 0; mt < 4; mt++)
#pragma unroll
        for (int nt = 0; nt < 4; nt++)
#pragma unroll
            for (int q = 0; q < 4; q++) acc[mt][nt][q] = 0.f;

    const int NT = K / BK;

    for (int kt = 0; kt < NT; kt++) {
#pragma unroll
        for (int i = 0; i < 4; i++) {
            float4 va = *(const float4*)(Aload + (size_t)kt * BK + (size_t)i * 32 * K);
            float4 vb = *(const float4*)(Bload + (size_t)kt * BK + (size_t)i * 32 * K);
            int m = lr + i * 32;
            float a4[4] = {va.x, va.y, va.z, va.w};
            float b4[4] = {vb.x, vb.y, vb.z, vb.w};
#pragma unroll
            for (int q = 0; q < 4; q++) {
                float hi, lo;
                split_cvt(a4[q], hi, lo);
                Ah[(lc4 * 4 + q) * SAPAD + m] = hi;
                Al[(lc4 * 4 + q) * SAPAD + m] = lo;
                split_cvt(b4[q], hi, lo);
                Bh[(lc4 * 4 + q) * SAPAD + m] = hi;
                Bl[(lc4 * 4 + q) * SAPAD + m] = lo;
            }
        }
        __syncthreads();

#pragma unroll
        for (int ks = 0; ks < 4; ks++) {
            int kb = ks * 8;
            uint32_t ah[4][4], al[4][4];
#pragma unroll
            for (int mt = 0; mt < 4; mt++) {
                int m0 = wm * 64 + mt * 16 + gID;
                ah[mt][0] = __float_as_uint(Ah[(kb + tig    ) * SAPAD + m0    ]);
                ah[mt][1] = __float_as_uint(Ah[(kb + tig    ) * SAPAD + m0 + 8]);
                ah[mt][2] = __float_as_uint(Ah[(kb + tig + 4) * SAPAD + m0    ]);
                ah[mt][3] = __float_as_uint(Ah[(kb + tig + 4) * SAPAD + m0 + 8]);
                al[mt][0] = __float_as_uint(Al[(kb + tig    ) * SAPAD + m0    ]);
                al[mt][1] = __float_as_uint(Al[(kb + tig    ) * SAPAD + m0 + 8]);
                al[mt][2] = __float_as_uint(Al[(kb + tig + 4) * SAPAD + m0    ]);
                al[mt][3] = __float_as_uint(Al[(kb + tig + 4) * SAPAD + m0 + 8]);
            }
#pragma unroll
            for (int nt = 0; nt < 4; nt++) {
                int n0 = wn * 32 + nt * 8 + gID;
                uint32_t bh0 = __float_as_uint(Bh[(kb + tig    ) * SAPAD + n0]);
                uint32_t bh1 = __float_as_uint(Bh[(kb + tig + 4) * SAPAD + n0]);
                uint32_t bl0 = __float_as_uint(Bl[(kb + tig    ) * SAPAD + n0]);
                uint32_t bl1 = __float_as_uint(Bl[(kb + tig + 4) * SAPAD + n0]);
#pragma unroll
                for (int mt = 0; mt < 4; mt++) {
                    mma_tf32(acc[mt][nt], ah[mt][0], ah[mt][1], ah[mt][2], ah[mt][3], bh0, bh1);
                    mma_tf32(acc[mt][nt], al[mt][0], al[mt][1], al[mt][2], al[mt][3], bh0, bh1);
                    mma_tf32(acc[mt][nt], ah[mt][0], ah[mt][1], ah[mt][2], ah[mt][3], bl0, bl1);
                }
            }
        }
        __syncthreads();
    }

#pragma unroll
    for (int mt = 0; mt < 4; mt++) {
#pragma unroll
        for (int nt = 0; nt < 4; nt++) {
            int r0 = rowBase + wm * 64 + mt * 16 + gID;
            int c0 = colBase + wn * 32 + nt * 8 + tig * 2;
            float bi0 = bias ? bias[c0] : 0.f;
            float bi1 = bias ? bias[c0 + 1] : 0.f;
            float* p0 = C + (size_t)r0 * N + c0;
            float* p1 = C + (size_t)(r0 + 8) * N + c0;
            *(float2*)p0 = make_float2(acc[mt][nt][0] + bi0, acc[mt][nt][1] + bi1);
            *(float2*)p1 = make_float2(acc[mt][nt][2] + bi0, acc[mt][nt][3] + bi1);
        }
    }
}

// =====================================================================
// Persistent RNN recurrence: one launch runs all 128 steps of a layer.
// 128 blocks (all co-resident), block owns 8 output columns; W slice in smem.
// Grid barrier: per-block flag + release store + acquire poll.
// h math exact fp32. h loads use ld.global.cv (bypass stale L1).
// =====================================================================
__device__ __forceinline__ void st_release_int(int* p, int v)
{
    asm volatile("st.release.gpu.global.s32 [%0], %1;" :: "l"(p), "r"(v) : "memory");
}
__device__ __forceinline__ int ld_acquire_int(const int* p)
{
    int v;
    asm volatile("ld.acquire.gpu.global.s32 %0, [%1];" : "=r"(v) : "l"(p) : "memory");
    return v;
}

__global__ void reset_flags_k()
{
    g_flags[threadIdx.x] = 0;
}

__global__ __launch_bounds__(256)
void rnn_persist(const float* __restrict__ xw,   // [128][32][1024]
                 const float* __restrict__ Whh,  // [1024][1024]
                 const float* __restrict__ bhh,  // [1024]
                 float* __restrict__ yseq)       // [128][32][1024]
{
    __shared__ float sw[8][HID];        // 32 KB W slice
    __shared__ float sb[8];
    __shared__ float red[8][BATCH][8];  // 8 KB partials

    int tid = threadIdx.x;
    int bid = blockIdx.x;
    int jbase = bid * 8;

    // load persistent W slice + bias
    for (int i = tid; i < 8 * HID / 4; i += 256) {
        int j = i >> 8, c = i & 255;
        *(float4*)&sw[j][c * 4] =
            *(const float4*)(Whh + (size_t)(jbase + j) * HID + c * 4);
    }
    if (tid < 8) sb[tid] = bhh[jbase + tid];
    __syncthreads();

    int w = tid >> 5;        // warp 0..7 -> k-slice
    int lane = tid & 31;     // lane -> batch row
    int kbase = w * 128;
    int rb = tid >> 3;       // reduce mapping: batch
    int rj = tid & 7;        // reduce mapping: local j

    const float* hrow0 = g_h + (size_t)lane * HID + kbase;

#pragma unroll 1
    for (int t = 0; t < T_LEN; t++) {
        const float* hrow = hrow0 + (size_t)(t & 1) * BATCH * HID;
        float* hnxt = g_h + (size_t)((t + 1) & 1) * BATCH * HID;

        float acc[8];
#pragma unroll
        for (int j = 0; j < 8; j++) acc[j] = 0.f;

#pragma unroll
        for (int c = 0; c < 4; c++) {
            float4 hv[8];
#pragma unroll
            for (int i = 0; i < 8; i++)
                hv[i] = __ldcv((const float4*)(hrow + c * 32 + i * 4));
#pragma unroll
            for (int i = 0; i < 8; i++) {
                int k = kbase + c * 32 + i * 4;
#pragma unroll
                for (int j = 0; j < 8; j++) {
                    float4 wv = *(const float4*)&sw[j][k];
                    acc[j] += wv.x * hv[i].x + wv.y * hv[i].y
                            + wv.z * hv[i].z + wv.w * hv[i].w;
                }
            }
        }

        // cross-warp (k-slice) reduction
        *(float4*)&red[w][lane][0] = make_float4(acc[0], acc[1], acc[2], acc[3]);
        *(float4*)&red[w][lane][4] = make_float4(acc[4], acc[5], acc[6], acc[7]);
        __syncthreads();
        {
            float s = 0.f;
#pragma unroll
            for (int ww = 0; ww < 8; ww++) s += red[ww][rb][rj];
            float pre = s + sb[rj] + xw[(size_t)t * BATCH * HID + rb * HID + jbase + rj];
            float v = tanhf(pre);
            hnxt[(size_t)rb * HID + jbase + rj] = v;
            yseq[(size_t)t * BATCH * HID + rb * HID + jbase + rj] = v;
        }

        // grid barrier
        __threadfence();
        __syncthreads();
        if (tid == 0) st_release_int(&g_flags[bid], t + 1);
        if (tid < 128) {
            while (ld_acquire_int(&g_flags[tid]) < t + 1) { }
        }
        __syncthreads();
    }
}

// =====================================================================
// In-place log_softmax over rows of 32000. Row cached in 128 KB smem.
// =====================================================================
__global__ __launch_bounds__(256)
void logsoftmax_k(float* __restrict__ out)
{
    extern __shared__ float srow[];
    __shared__ float red[256];
    int tid = threadIdx.x;
    float4* p4 = (float4*)(out + (size_t)blockIdx.x * VOCAB);

    float m = -3.4e38f;
    for (int i = tid; i < VOCAB / 4; i += 256) {
        float4 v = p4[i];
        *(float4*)&srow[i * 4] = v;
        m = fmaxf(m, fmaxf(fmaxf(v.x, v.y), fmaxf(v.z, v.w)));
    }
    red[tid] = m; __syncthreads();
    for (int s = 128; s > 0; s >>= 1) {
        if (tid < s) red[tid] = fmaxf(red[tid], red[tid + s]);
        __syncthreads();
    }
    float rm = red[0]; __syncthreads();

    float sum = 0.f;
    for (int i = tid; i < VOCAB; i += 256) sum += expf(srow[i] - rm);
    red[tid] = sum; __syncthreads();
    for (int s = 128; s > 0; s >>= 1) {
        if (tid < s) red[tid] += red[tid + s];
        __syncthreads();
    }
    float lz = rm + logf(red[0]);

    for (int i = tid; i < VOCAB / 4; i += 256) {
        float4 v = *(float4*)&srow[i * 4];
        v.x -= lz; v.y -= lz; v.z -= lz; v.w -= lz;
        p4[i] = v;
    }
}

// =====================================================================
// host orchestration (graph-capturable)
// =====================================================================
extern "C" void kernel_launch(void* const* d_in, const int* in_sizes, int n_in,
                              void* d_out, int out_size)
{
    const int*   input_x = (const int*)  d_in[0];
    const float* hidden  = (const float*)d_in[1];
    const float* emb     = (const float*)d_in[2];
    const float* W_ih    = (const float*)d_in[3];
    const float* W_hh    = (const float*)d_in[4];
    const float* b_ih    = (const float*)d_in[5];
    const float* b_hh    = (const float*)d_in[6];
    const float* W_out   = (const float*)d_in[7];
    const float* b_out   = (const float*)d_in[8];
    float* out = (float*)d_out;

    float *gx, *gxw, *gh;
    cudaGetSymbolAddress((void**)&gx,  g_x);
    cudaGetSymbolAddress((void**)&gxw, g_xw);
    cudaGetSymbolAddress((void**)&gh,  g_h);

    static int attr_done = 0;
    if (!attr_done) {
        cudaFuncSetAttribute(logsoftmax_k,
                             cudaFuncAttributeMaxDynamicSharedMemorySize,
                             VOCAB * (int)sizeof(float));
        cudaFuncSetAttribute(gemm_split3,
                             cudaFuncAttributeMaxDynamicSharedMemorySize,
                             4 * BK * SAPAD * (int)sizeof(float));
        attr_done = 1;
    }

    const int writeHidden = (size_t)out_size >= LOGITS_ELEMS + HIDDEN_ELEMS;

    // 1) embedding gather
    embed_k<<<MROWS, 256>>>(input_x, emb, gx);

    for (int l = 0; l < 2; l++) {
        const float* Wi = W_ih + (size_t)l * HID * HID;
        const float* Wh = W_hh + (size_t)l * HID * HID;
        const float* bi = b_ih + (size_t)l * HID;
        const float* bh = b_hh + (size_t)l * HID;

        // init hidden into ping-pong slot 0
        cudaMemcpyAsync(gh, hidden + (size_t)l * BATCH * HID,
                        (size_t)BATCH * HID * sizeof(float),
                        cudaMemcpyDeviceToDevice, 0);

        // input projection: fused 3-term tf32 split, single launch
        dim3 gp(MROWS / BM, HID / BN);
        gemm_split3<<<gp, 256, 4 * BK * SAPAD * (int)sizeof(float)>>>(
            gx, Wi, gxw, bi, MROWS, HID, HID);

        // persistent recurrence (exact fp32)
        reset_flags_k<<<1, 128>>>();
        rnn_persist<<<128, 256>>>(gxw, Wh, bh, gx);

        // new_hidden[l] = y[T-1]
        if (writeHidden)
            cudaMemcpyAsync(out + LOGITS_ELEMS + (size_t)l * BATCH * HID,
                            gx + (size_t)(T_LEN - 1) * BATCH * HID,
                            (size_t)BATCH * HID * sizeof(float),
                            cudaMemcpyDeviceToDevice, 0);
    }

    // output projection (single-pass tf32, no downstream accumulation)
    dim3 go(MROWS / BM, VOCAB / BN);
    gemm_tf32<<<go, 256>>>(gx, W_out, out, b_out, MROWS, VOCAB, HID);

    // in-place log_softmax
    logsoftmax_k<<<MROWS, 256, VOCAB * (int)sizeof(float)>>>(out);
}